// round 16
// baseline (speedup 1.0000x reference)
#include <cuda_runtime.h>
#include <cstdint>
#include <cstddef>

#define NN 100000              // nodes
#define NNP 100096             // nodes padded to 782*128 for GEMM tiles
#define NR 6                   // relations
#define EP 100000              // edges per relation
#define NE (NR*EP)             // total edges
#define HH 256                 // hidden
#define NG 128                 // graphs
#define KT 1792                // 7*256 concat K for the big GEMM

// ---------------- scratch (device globals; no runtime allocation) ----------
static __device__ float g_A [(size_t)NNP*KT];   // GEMM input (padded rows)
static __device__ float g_h1[(size_t)NN*HH];    // layer0 output
static __device__ float g_h2[(size_t)NN*HH];    // layer1 output
static __device__ float g_Bt[(size_t)HH*KT];    // B transposed: [N=256][K=1792]
static __device__ float g_Pt[7*4*HH];           // type tables (6 rel + self)
static __device__ float g_Ps[7*256*HH];         // subtype tables
static __device__ int   g_deg[NN];
static __device__ float g_inv[NN];
static __device__ int   g_cur[NR*NN];           // histogram / scatter cursor
static __device__ int   g_off[NR*NN+1];         // CSR offsets per (rel,tgt)
static __device__ int   g_srcs[NE];             // src ids grouped by (rel,tgt)
static __device__ int   g_gs[NG+1];             // graph segment starts
static __device__ float g_pool[NG*HH];
static __device__ float g_z[NG*HH];

// ---------------- float4 helpers ----------------
__device__ __forceinline__ float4 f4add(float4 a, float4 b){
    return make_float4(a.x+b.x, a.y+b.y, a.z+b.z, a.w+b.w);
}
__device__ __forceinline__ float4 f4fma1(float4 a, float s, float4 c){
    return make_float4(fmaf(a.x,s,c.x), fmaf(a.y,s,c.y), fmaf(a.z,s,c.z), fmaf(a.w,s,c.w));
}
__device__ __forceinline__ float4 f4scale(float4 a, float s){
    return make_float4(a.x*s, a.y*s, a.z*s, a.w*s);
}
__device__ __forceinline__ float4 f4relu(float4 a){
    return make_float4(fmaxf(a.x,0.f), fmaxf(a.y,0.f), fmaxf(a.z,0.f), fmaxf(a.w,0.f));
}

// ---------------- cp.async helpers ----------------
__device__ __forceinline__ uint32_t smem_u32(const void* p){
    uint32_t a;
    asm("{ .reg .u64 t; cvta.to.shared.u64 t, %1; cvt.u32.u64 %0, t; }" : "=r"(a) : "l"(p));
    return a;
}
#define CP_ASYNC16(dst, src) \
    asm volatile("cp.async.cg.shared.global [%0], [%1], 16;" :: "r"(dst), "l"(src) : "memory")
#define CP_COMMIT() asm volatile("cp.async.commit_group;" ::: "memory")
#define CP_WAIT2()  asm volatile("cp.async.wait_group 2;" ::: "memory")

// tf32 mma.sync (sm_80+; compiles for plain compute_103)
#define MMA_TF32(d, a, b) \
    asm volatile("mma.sync.aligned.m16n8k8.row.col.f32.tf32.tf32.f32 " \
        "{%0,%1,%2,%3}, {%4,%5,%6,%7}, {%8,%9}, {%0,%1,%2,%3};" \
        : "+f"((d)[0]), "+f"((d)[1]), "+f"((d)[2]), "+f"((d)[3]) \
        : "r"((a)[0]), "r"((a)[1]), "r"((a)[2]), "r"((a)[3]), \
          "r"((b)[0]), "r"((b)[1]))

// ---------------- init / CSR build ----------------
__global__ void k_init()
{
    int i = blockIdx.x*blockDim.x + threadIdx.x;
    if (i < NR*NN) g_cur[i] = 0;
    if (i < NN)    g_deg[i] = 0;
}

__global__ void k_hist(const int* __restrict__ edges)
{
    int i = blockIdx.x*blockDim.x + threadIdx.x;
    if (i >= NE) return;
    int r = i / EP, e = i - r*EP;
    int tgt = edges[r*2*EP + EP + e];
    atomicAdd(&g_deg[tgt], 1);
    atomicAdd(&g_cur[r*NN + tgt], 1);
}

__global__ void k_inv()
{
    int i = blockIdx.x*blockDim.x + threadIdx.x;
    if (i >= NN) return;
    int d = g_deg[i];
    g_inv[i] = 1.f / (float)(d > 0 ? d : 1);
}

// single-CTA exclusive scan of g_cur[0..NR*NN) -> g_off (and reset g_cur=offsets)
__global__ void k_scan()
{
    const int total = NR*NN;
    __shared__ int wsum[32];
    __shared__ int s_carry;
    int tid = threadIdx.x;                 // 1024 threads
    if (tid == 0) s_carry = 0;
    __syncthreads();
    const int CH = 1024*8;
    for (int base = 0; base < total; base += CH){
        int i0 = base + tid*8;
        int v[8];
        int s8 = 0;
        #pragma unroll
        for (int j = 0; j < 8; j++){
            int i = i0 + j;
            v[j] = (i < total) ? g_cur[i] : 0;
            s8 += v[j];
        }
        int x = s8;
        #pragma unroll
        for (int o = 1; o < 32; o <<= 1){
            int y = __shfl_up_sync(0xffffffffu, x, o);
            if ((tid & 31) >= o) x += y;
        }
        if ((tid & 31) == 31) wsum[tid >> 5] = x;
        __syncthreads();
        if (tid < 32){
            int wv = wsum[tid];
            #pragma unroll
            for (int o = 1; o < 32; o <<= 1){
                int y = __shfl_up_sync(0xffffffffu, wv, o);
                if (tid >= o) wv += y;
            }
            wsum[tid] = wv;
        }
        __syncthreads();
        int woff = (tid >= 32) ? wsum[(tid >> 5) - 1] : 0;
        int incl = x + woff;
        int run  = s_carry + incl - s8;
        #pragma unroll
        for (int j = 0; j < 8; j++){
            int i = i0 + j;
            if (i < total){ g_off[i] = run; g_cur[i] = run; }
            run += v[j];
        }
        __syncthreads();
        if (tid == 1023) s_carry += incl;
        __syncthreads();
    }
    if (tid == 0) g_off[total] = s_carry;
}

__global__ void k_scatter(const int* __restrict__ edges)
{
    int i = blockIdx.x*blockDim.x + threadIdx.x;
    if (i >= NE) return;
    int r = i / EP, e = i - r*EP;
    int src = edges[r*2*EP + e];
    int tgt = edges[r*2*EP + EP + e];
    int pos = atomicAdd(&g_cur[r*NN + tgt], 1);
    g_srcs[pos] = src;
}

// ---------------- layer-0 lookup tables ----------------
__global__ void k_tables(const float* __restrict__ type_emb, const float* __restrict__ sub_emb,
                         const float* __restrict__ W_rel0, const float* __restrict__ W_self0)
{
    int m   = blockIdx.x;      // 0..6
    int row = blockIdx.y;      // 0..259 (0..3 type, 4..259 sub)
    int d   = threadIdx.x;     // 0..255
    const float* W = (m < 6) ? (W_rel0 + (size_t)m*HH*HH) : W_self0;
    float acc = 0.f;
    if (row < 4){
        const float* e = type_emb + row*128;
        #pragma unroll 8
        for (int k = 0; k < 128; k++) acc = fmaf(e[k], W[(size_t)k*HH + d], acc);
        g_Pt[(m*4 + row)*HH + d] = acc;
    } else {
        int s = row - 4;
        const float* e = sub_emb + s*128;
        #pragma unroll 8
        for (int k = 0; k < 128; k++) acc = fmaf(e[k], W[(size_t)(128+k)*HH + d], acc);
        g_Ps[(m*256 + s)*HH + d] = acc;
    }
}

// ---------------- layer 0 (entire layer via tables; warp per node) ----------
__global__ void k_layer0(const int* __restrict__ x_type, const int* __restrict__ x_sub,
                         const float* __restrict__ b0)
{
    int w = (blockIdx.x*blockDim.x + threadIdx.x) >> 5;
    if (w >= NN) return;
    int lane = threadIdx.x & 31;
    int c0 = lane*8;
    float4 a0 = make_float4(0,0,0,0), a1 = a0;
    #pragma unroll
    for (int r = 0; r < NR; r++){
        int o0 = g_off[r*NN + w];
        int o1 = g_off[r*NN + w + 1];
        for (int e = o0; e < o1; e++){
            int s  = g_srcs[e];
            int ty = x_type[s];
            int su = x_sub[s];
            const float4* pt = (const float4*)&g_Pt[(r*4 + ty)*HH + c0];
            const float4* ps = (const float4*)&g_Ps[(r*256 + su)*HH + c0];
            a0 = f4add(a0, f4add(pt[0], ps[0]));
            a1 = f4add(a1, f4add(pt[1], ps[1]));
        }
    }
    float inv = g_inv[w];
    int ty = x_type[w], su = x_sub[w];
    const float4* pt = (const float4*)&g_Pt[(6*4 + ty)*HH + c0];
    const float4* ps = (const float4*)&g_Ps[(6*256 + su)*HH + c0];
    const float4* bb = (const float4*)&b0[c0];
    float4 o0v = f4relu(f4fma1(a0, inv, f4add(f4add(pt[0], ps[0]), bb[0])));
    float4 o1v = f4relu(f4fma1(a1, inv, f4add(f4add(pt[1], ps[1]), bb[1])));
    float4* outp = (float4*)&g_h1[(size_t)w*HH + c0];
    outp[0] = o0v; outp[1] = o1v;
}

// ---------------- layer-1 aggregation: build A = [invdeg*sum_r | self] -----
__global__ void k_agg1()
{
    int w = (blockIdx.x*blockDim.x + threadIdx.x) >> 5;
    if (w >= NN) return;
    int lane = threadIdx.x & 31;
    int c0 = lane*8;
    float inv = g_inv[w];
    const float4* hs = (const float4*)&g_h1[(size_t)w*HH + c0];
    float4* aself = (float4*)&g_A[(size_t)w*KT + 6*HH + c0];
    aself[0] = hs[0]; aself[1] = hs[1];
    #pragma unroll
    for (int r = 0; r < NR; r++){
        int o0 = g_off[r*NN + w];
        int o1 = g_off[r*NN + w + 1];
        float4 a0 = make_float4(0,0,0,0), a1 = a0;
        for (int e = o0; e < o1; e++){
            int s = g_srcs[e];
            const float4* hv = (const float4*)&g_h1[(size_t)s*HH + c0];
            a0 = f4add(a0, hv[0]);
            a1 = f4add(a1, hv[1]);
        }
        float4* dst = (float4*)&g_A[(size_t)w*KT + r*HH + c0];
        dst[0] = f4scale(a0, inv);
        dst[1] = f4scale(a1, inv);
    }
}

// ---------------- stack + transpose W_rel1 / W_self1 into g_Bt[N][K] -------
__global__ void k_copyBt(const float* __restrict__ W_rel1, const float* __restrict__ W_self1)
{
    int i = blockIdx.x*blockDim.x + threadIdx.x;
    if (i >= KT*HH) return;
    int k = i / HH, n = i - k*HH;
    float v = (k < 1536) ? W_rel1[i] : W_self1[i - 1536*HH];
    g_Bt[(size_t)n*KT + k] = v;
}

// ---------------- tf32 mma.sync GEMM: h2 = relu(A @ B + b1) ----------------
// M = NNP (128/CTA), N = 256 (full), K = 1792 in BK=32 stages, 3-stage ring.
#define BM 128
#define BN 256
#define BK 32
#define LDT 36                          // padded smem row stride (floats)
#define A_STG (BM*LDT)                  // 4608 floats / stage
#define B_STG (BN*LDT)                  // 9216 floats / stage
#define STG_FLT (A_STG + B_STG)         // 13824 floats
#define NSTG (KT/BK)                    // 56
#define SMEM_GEMM (3*STG_FLT*4)         // 165888 bytes

__global__ void __launch_bounds__(256, 1) k_gemm_mma(const float* __restrict__ bias)
{
    extern __shared__ float sm[];
    const uint32_t smb = smem_u32(sm);
    const int tid  = threadIdx.x;
    const int brow = blockIdx.x * BM;
    const int w    = tid >> 5;
    const int lane = tid & 31;
    const int g    = lane >> 2;        // 0..7
    const int r    = lane & 3;         // 0..3
    const int warpM = (w >> 2) * 64;   // 0 / 64
    const int warpN = (w & 3) * 64;    // 0 / 64 / 128 / 192

    // --- per-thread cp.async plan (byte offsets within a stage) ---
    const float* a_src[4]; uint32_t a_dst[4];
    #pragma unroll
    for (int i = 0; i < 4; i++){
        int c = tid + i*256;           // 0..1023  (128 rows x 8 quads)
        int row = c >> 3, q = c & 7;
        a_src[i] = g_A + (size_t)(brow + row)*KT + q*4;
        a_dst[i] = (uint32_t)(row*LDT + q*4) * 4;
    }
    const float* b_src[8]; uint32_t b_dst[8];
    #pragma unroll
    for (int i = 0; i < 8; i++){
        int c = tid + i*256;           // 0..2047  (256 rows x 8 quads)
        int row = c >> 3, q = c & 7;
        b_src[i] = g_Bt + (size_t)row*KT + q*4;
        b_dst[i] = (uint32_t)(A_STG + row*LDT + q*4) * 4;
    }

    #define LOAD_STAGE(s) do { \
        uint32_t _b = smb + (uint32_t)((s) % 3) * (STG_FLT*4); \
        int _k = (s) * BK; \
        _Pragma("unroll") \
        for (int _i = 0; _i < 4; _i++) CP_ASYNC16(_b + a_dst[_i], a_src[_i] + _k); \
        _Pragma("unroll") \
        for (int _i = 0; _i < 8; _i++) CP_ASYNC16(_b + b_dst[_i], b_src[_i] + _k); \
    } while(0)

    float acc[4][8][4];
    #pragma unroll
    for (int i = 0; i < 4; i++)
        #pragma unroll
        for (int j = 0; j < 8; j++)
            #pragma unroll
            for (int q = 0; q < 4; q++) acc[i][j][q] = 0.f;

    LOAD_STAGE(0); CP_COMMIT();
    LOAD_STAGE(1); CP_COMMIT();

    for (int t = 0; t < NSTG; t++){
        if (t + 2 < NSTG) LOAD_STAGE(t + 2);
        CP_COMMIT();                   // empty group at tail keeps counting uniform
        CP_WAIT2();                    // stage t complete
        __syncthreads();
        const uint32_t* As = (const uint32_t*)(sm + (t % 3) * STG_FLT);
        const uint32_t* Bs = As + A_STG;
        #pragma unroll
        for (int kk = 0; kk < BK; kk += 8){
            uint32_t a[4][4], b[8][2];
            #pragma unroll
            for (int i = 0; i < 4; i++){
                int m = warpM + i*16 + g;
                a[i][0] = As[m*LDT + kk + r];
                a[i][1] = As[(m+8)*LDT + kk + r];
                a[i][2] = As[m*LDT + kk + 4 + r];
                a[i][3] = As[(m+8)*LDT + kk + 4 + r];
            }
            #pragma unroll
            for (int j = 0; j < 8; j++){
                int n = warpN + j*8 + g;
                b[j][0] = Bs[n*LDT + kk + r];
                b[j][1] = Bs[n*LDT + kk + 4 + r];
            }
            #pragma unroll
            for (int i = 0; i < 4; i++)
                #pragma unroll
                for (int j = 0; j < 8; j++)
                    MMA_TF32(acc[i][j], a[i], b[j]);
        }
        __syncthreads();               // protect buffer (t%3) before reuse at t+1
    }

    // --- epilogue: bias + relu ---
    #pragma unroll
    for (int i = 0; i < 4; i++){
        int row0 = brow + warpM + i*16 + g;
        int row1 = row0 + 8;
        #pragma unroll
        for (int j = 0; j < 8; j++){
            int col = warpN + j*8 + 2*r;
            float bx = __ldg(&bias[col]);
            float by = __ldg(&bias[col+1]);
            if (row0 < NN){
                float2 v;
                v.x = fmaxf(acc[i][j][0] + bx, 0.f);
                v.y = fmaxf(acc[i][j][1] + by, 0.f);
                *(float2*)&g_h2[(size_t)row0*HH + col] = v;
            }
            if (row1 < NN){
                float2 v;
                v.x = fmaxf(acc[i][j][2] + bx, 0.f);
                v.y = fmaxf(acc[i][j][3] + by, 0.f);
                *(float2*)&g_h2[(size_t)row1*HH + col] = v;
            }
        }
    }
    #undef LOAD_STAGE
}

// ---------------- mean pool (batch_ids sorted -> segment starts) ----------
__global__ void k_gstart(const int* __restrict__ batch_ids)
{
    int i = blockIdx.x*blockDim.x + threadIdx.x;
    if (i >= NN) return;
    int b    = batch_ids[i];
    int prev = (i == 0) ? -1 : batch_ids[i-1];
    for (int g = prev + 1; g <= b; g++) g_gs[g] = i;
    if (i == NN-1)
        for (int g = b + 1; g <= NG; g++) g_gs[g] = NN;
}

__global__ void k_pool()
{
    int g = blockIdx.x, c = threadIdx.x;
    int s = g_gs[g], e = g_gs[g+1];
    float s0 = 0.f, s1 = 0.f, s2 = 0.f, s3 = 0.f;
    int i = s;
    for (; i + 3 < e; i += 4){
        s0 += g_h2[(size_t)(i  )*HH + c];
        s1 += g_h2[(size_t)(i+1)*HH + c];
        s2 += g_h2[(size_t)(i+2)*HH + c];
        s3 += g_h2[(size_t)(i+3)*HH + c];
    }
    for (; i < e; i++) s0 += g_h2[(size_t)i*HH + c];
    float sum = (s0 + s1) + (s2 + s3);
    int cnt = e - s; if (cnt < 1) cnt = 1;
    g_pool[g*HH + c] = sum / (float)cnt;
}

// ---------------- final MLP (tiny) ----------------
__global__ void k_mlp(const float* __restrict__ W, const float* __restrict__ bias,
                      float* __restrict__ outp, int mode)
{
    __shared__ float xr[HH];
    int g = blockIdx.x, c = threadIdx.x;
    xr[c] = (mode == 0) ? g_pool[g*HH + c] : g_z[g*HH + c];
    __syncthreads();
    float acc = bias[c];
    #pragma unroll 8
    for (int k = 0; k < HH; k++) acc = fmaf(xr[k], W[(size_t)k*HH + c], acc);
    if (mode == 0) g_z[g*HH + c] = fmaxf(acc, 0.f);
    else           outp[g*HH + c] = acc;
}

// ---------------- launch ----------------
extern "C" void kernel_launch(void* const* d_in, const int* in_sizes, int n_in,
                              void* d_out, int out_size)
{
    const int* x_type    = (const int*)d_in[0];
    const int* x_sub     = (const int*)d_in[1];
    const int* edges     = (const int*)d_in[2];
    const int* batch_ids = (const int*)d_in[3];
    int idx = 4;
    if (idx < n_in && in_sizes[idx] == 1) idx++;   // skip n_graphs scalar if passed
    const float* type_emb = (const float*)d_in[idx++];
    const float* sub_emb  = (const float*)d_in[idx++];
    const float* W_rel0   = (const float*)d_in[idx++];
    const float* W_self0  = (const float*)d_in[idx++];
    const float* b0       = (const float*)d_in[idx++];
    const float* W_rel1   = (const float*)d_in[idx++];
    const float* W_self1  = (const float*)d_in[idx++];
    const float* b1       = (const float*)d_in[idx++];
    const float* pW1      = (const float*)d_in[idx++];
    const float* pb1      = (const float*)d_in[idx++];
    const float* pW2      = (const float*)d_in[idx++];
    const float* pb2      = (const float*)d_in[idx++];
    float* out = (float*)d_out;

    cudaFuncSetAttribute(k_gemm_mma, cudaFuncAttributeMaxDynamicSharedMemorySize, SMEM_GEMM);

    k_init    <<<(NR*NN + 255)/256, 256>>>();
    k_tables  <<<dim3(7, 260), 256>>>(type_emb, sub_emb, W_rel0, W_self0);
    k_copyBt  <<<(KT*HH + 255)/256, 256>>>(W_rel1, W_self1);
    k_hist    <<<(NE + 255)/256, 256>>>(edges);
    k_inv     <<<(NN + 255)/256, 256>>>();
    k_scan    <<<1, 1024>>>();
    k_scatter <<<(NE + 255)/256, 256>>>(edges);
    k_layer0  <<<(NN*32 + 255)/256, 256>>>(x_type, x_sub, b0);
    k_agg1    <<<(NN*32 + 255)/256, 256>>>();
    k_gemm_mma<<<NNP/128, 256, SMEM_GEMM>>>(b1);
    k_gstart  <<<(NN + 255)/256, 256>>>(batch_ids);
    k_pool    <<<NG, 256>>>();
    k_mlp     <<<NG, 256>>>(pW1, pb1, (float*)0, 0);
    k_mlp     <<<NG, 256>>>(pW2, pb2, out, 1);
}

// round 17
// speedup vs baseline: 1.0003x; 1.0003x over previous
#include <cuda_runtime.h>
#include <cstdint>
#include <cstddef>

#define NN 100000              // nodes
#define NNP 100096             // nodes padded to 782*128 for GEMM tiles
#define NR 6                   // relations
#define EP 100000              // edges per relation
#define NE (NR*EP)             // total edges
#define HH 256                 // hidden
#define NG 128                 // graphs
#define KT 1792                // 7*256 concat K for the big GEMM

// ---------------- scratch (device globals; no runtime allocation) ----------
static __device__ float g_A [(size_t)NNP*KT];   // GEMM input (padded rows)
static __device__ float g_h1[(size_t)NN*HH];    // layer0 output
static __device__ float g_h2[(size_t)NN*HH];    // layer1 output
static __device__ float g_Bt[(size_t)HH*KT];    // B transposed: [N=256][K=1792]
static __device__ float g_Pt[7*4*HH];           // type tables (6 rel + self)
static __device__ float g_Ps[7*256*HH];         // subtype tables
static __device__ int   g_deg[NN];
static __device__ float g_inv[NN];
static __device__ int   g_cur[NR*NN];           // histogram / scatter cursor
static __device__ int   g_off[NR*NN+1];         // CSR offsets per (rel,tgt)
static __device__ int   g_srcs[NE];             // src ids grouped by (rel,tgt)
static __device__ int   g_gs[NG+1];             // graph segment starts
static __device__ float g_pool[NG*HH];
static __device__ float g_z[NG*HH];

// ---------------- float4 helpers ----------------
__device__ __forceinline__ float4 f4add(float4 a, float4 b){
    return make_float4(a.x+b.x, a.y+b.y, a.z+b.z, a.w+b.w);
}
__device__ __forceinline__ float4 f4fma1(float4 a, float s, float4 c){
    return make_float4(fmaf(a.x,s,c.x), fmaf(a.y,s,c.y), fmaf(a.z,s,c.z), fmaf(a.w,s,c.w));
}
__device__ __forceinline__ float4 f4scale(float4 a, float s){
    return make_float4(a.x*s, a.y*s, a.z*s, a.w*s);
}
__device__ __forceinline__ float4 f4relu(float4 a){
    return make_float4(fmaxf(a.x,0.f), fmaxf(a.y,0.f), fmaxf(a.z,0.f), fmaxf(a.w,0.f));
}

// ---------------- cp.async helpers ----------------
__device__ __forceinline__ uint32_t smem_u32(const void* p){
    uint32_t a;
    asm("{ .reg .u64 t; cvta.to.shared.u64 t, %1; cvt.u32.u64 %0, t; }" : "=r"(a) : "l"(p));
    return a;
}
#define CP_ASYNC16(dst, src) \
    asm volatile("cp.async.cg.shared.global [%0], [%1], 16;" :: "r"(dst), "l"(src) : "memory")
#define CP_COMMIT() asm volatile("cp.async.commit_group;" ::: "memory")
#define CP_WAIT2()  asm volatile("cp.async.wait_group 2;" ::: "memory")

// tf32 mma.sync (sm_80+; compiles for plain compute_103)
#define MMA_TF32(d, a, b) \
    asm volatile("mma.sync.aligned.m16n8k8.row.col.f32.tf32.tf32.f32 " \
        "{%0,%1,%2,%3}, {%4,%5,%6,%7}, {%8,%9}, {%0,%1,%2,%3};" \
        : "+f"((d)[0]), "+f"((d)[1]), "+f"((d)[2]), "+f"((d)[3]) \
        : "r"((a)[0]), "r"((a)[1]), "r"((a)[2]), "r"((a)[3]), \
          "r"((b)[0]), "r"((b)[1]))

// ---------------- init / CSR build ----------------
__global__ void k_init()
{
    int i = blockIdx.x*blockDim.x + threadIdx.x;
    if (i < NR*NN) g_cur[i] = 0;
    if (i < NN)    g_deg[i] = 0;
}

__global__ void k_hist(const int* __restrict__ edges)
{
    int i = blockIdx.x*blockDim.x + threadIdx.x;
    if (i >= NE) return;
    int r = i / EP, e = i - r*EP;
    int tgt = edges[r*2*EP + EP + e];
    atomicAdd(&g_deg[tgt], 1);
    atomicAdd(&g_cur[r*NN + tgt], 1);
}

__global__ void k_inv()
{
    int i = blockIdx.x*blockDim.x + threadIdx.x;
    if (i >= NN) return;
    int d = g_deg[i];
    g_inv[i] = 1.f / (float)(d > 0 ? d : 1);
}

// single-CTA exclusive scan of g_cur[0..NR*NN) -> g_off (and reset g_cur=offsets)
__global__ void k_scan()
{
    const int total = NR*NN;
    __shared__ int wsum[32];
    __shared__ int s_carry;
    int tid = threadIdx.x;                 // 1024 threads
    if (tid == 0) s_carry = 0;
    __syncthreads();
    const int CH = 1024*8;
    for (int base = 0; base < total; base += CH){
        int i0 = base + tid*8;
        int v[8];
        int s8 = 0;
        #pragma unroll
        for (int j = 0; j < 8; j++){
            int i = i0 + j;
            v[j] = (i < total) ? g_cur[i] : 0;
            s8 += v[j];
        }
        int x = s8;
        #pragma unroll
        for (int o = 1; o < 32; o <<= 1){
            int y = __shfl_up_sync(0xffffffffu, x, o);
            if ((tid & 31) >= o) x += y;
        }
        if ((tid & 31) == 31) wsum[tid >> 5] = x;
        __syncthreads();
        if (tid < 32){
            int wv = wsum[tid];
            #pragma unroll
            for (int o = 1; o < 32; o <<= 1){
                int y = __shfl_up_sync(0xffffffffu, wv, o);
                if (tid >= o) wv += y;
            }
            wsum[tid] = wv;
        }
        __syncthreads();
        int woff = (tid >= 32) ? wsum[(tid >> 5) - 1] : 0;
        int incl = x + woff;
        int run  = s_carry + incl - s8;
        #pragma unroll
        for (int j = 0; j < 8; j++){
            int i = i0 + j;
            if (i < total){ g_off[i] = run; g_cur[i] = run; }
            run += v[j];
        }
        __syncthreads();
        if (tid == 1023) s_carry += incl;
        __syncthreads();
    }
    if (tid == 0) g_off[total] = s_carry;
}

__global__ void k_scatter(const int* __restrict__ edges)
{
    int i = blockIdx.x*blockDim.x + threadIdx.x;
    if (i >= NE) return;
    int r = i / EP, e = i - r*EP;
    int src = edges[r*2*EP + e];
    int tgt = edges[r*2*EP + EP + e];
    int pos = atomicAdd(&g_cur[r*NN + tgt], 1);
    g_srcs[pos] = src;
}

// ---------------- layer-0 lookup tables ----------------
__global__ void k_tables(const float* __restrict__ type_emb, const float* __restrict__ sub_emb,
                         const float* __restrict__ W_rel0, const float* __restrict__ W_self0)
{
    int m   = blockIdx.x;      // 0..6
    int row = blockIdx.y;      // 0..259 (0..3 type, 4..259 sub)
    int d   = threadIdx.x;     // 0..255
    const float* W = (m < 6) ? (W_rel0 + (size_t)m*HH*HH) : W_self0;
    float acc = 0.f;
    if (row < 4){
        const float* e = type_emb + row*128;
        #pragma unroll 8
        for (int k = 0; k < 128; k++) acc = fmaf(e[k], W[(size_t)k*HH + d], acc);
        g_Pt[(m*4 + row)*HH + d] = acc;
    } else {
        int s = row - 4;
        const float* e = sub_emb + s*128;
        #pragma unroll 8
        for (int k = 0; k < 128; k++) acc = fmaf(e[k], W[(size_t)(128+k)*HH + d], acc);
        g_Ps[(m*256 + s)*HH + d] = acc;
    }
}

// ---------------- layer 0 (entire layer via tables; warp per node) ----------
__global__ void k_layer0(const int* __restrict__ x_type, const int* __restrict__ x_sub,
                         const float* __restrict__ b0)
{
    int w = (blockIdx.x*blockDim.x + threadIdx.x) >> 5;
    if (w >= NN) return;
    int lane = threadIdx.x & 31;
    int c0 = lane*8;
    float4 a0 = make_float4(0,0,0,0), a1 = a0;
    #pragma unroll
    for (int r = 0; r < NR; r++){
        int o0 = g_off[r*NN + w];
        int o1 = g_off[r*NN + w + 1];
        for (int e = o0; e < o1; e++){
            int s  = g_srcs[e];
            int ty = x_type[s];
            int su = x_sub[s];
            const float4* pt = (const float4*)&g_Pt[(r*4 + ty)*HH + c0];
            const float4* ps = (const float4*)&g_Ps[(r*256 + su)*HH + c0];
            a0 = f4add(a0, f4add(pt[0], ps[0]));
            a1 = f4add(a1, f4add(pt[1], ps[1]));
        }
    }
    float inv = g_inv[w];
    int ty = x_type[w], su = x_sub[w];
    const float4* pt = (const float4*)&g_Pt[(6*4 + ty)*HH + c0];
    const float4* ps = (const float4*)&g_Ps[(6*256 + su)*HH + c0];
    const float4* bb = (const float4*)&b0[c0];
    float4 o0v = f4relu(f4fma1(a0, inv, f4add(f4add(pt[0], ps[0]), bb[0])));
    float4 o1v = f4relu(f4fma1(a1, inv, f4add(f4add(pt[1], ps[1]), bb[1])));
    float4* outp = (float4*)&g_h1[(size_t)w*HH + c0];
    outp[0] = o0v; outp[1] = o1v;
}

// ---------------- layer-1 aggregation: build A = [invdeg*sum_r | self] -----
__global__ void k_agg1()
{
    int w = (blockIdx.x*blockDim.x + threadIdx.x) >> 5;
    if (w >= NN) return;
    int lane = threadIdx.x & 31;
    int c0 = lane*8;
    float inv = g_inv[w];
    const float4* hs = (const float4*)&g_h1[(size_t)w*HH + c0];
    float4* aself = (float4*)&g_A[(size_t)w*KT + 6*HH + c0];
    aself[0] = hs[0]; aself[1] = hs[1];
    #pragma unroll
    for (int r = 0; r < NR; r++){
        int o0 = g_off[r*NN + w];
        int o1 = g_off[r*NN + w + 1];
        float4 a0 = make_float4(0,0,0,0), a1 = a0;
        for (int e = o0; e < o1; e++){
            int s = g_srcs[e];
            const float4* hv = (const float4*)&g_h1[(size_t)s*HH + c0];
            a0 = f4add(a0, hv[0]);
            a1 = f4add(a1, hv[1]);
        }
        float4* dst = (float4*)&g_A[(size_t)w*KT + r*HH + c0];
        dst[0] = f4scale(a0, inv);
        dst[1] = f4scale(a1, inv);
    }
}

// ---------------- stack + transpose W_rel1 / W_self1 into g_Bt[N][K] -------
__global__ void k_copyBt(const float* __restrict__ W_rel1, const float* __restrict__ W_self1)
{
    int i = blockIdx.x*blockDim.x + threadIdx.x;
    if (i >= KT*HH) return;
    int k = i / HH, n = i - k*HH;
    float v = (k < 1536) ? W_rel1[i] : W_self1[i - 1536*HH];
    g_Bt[(size_t)n*KT + k] = v;
}

// ---------------- tf32 mma.sync GEMM: h2 = relu(A @ B + b1) ----------------
// M = NNP (128/CTA), N = 256 (full), K = 1792 in BK=32 stages, 3-stage ring.
#define BM 128
#define BN 256
#define BK 32
#define LDT 36                          // padded smem row stride (floats)
#define A_STG (BM*LDT)                  // 4608 floats / stage
#define B_STG (BN*LDT)                  // 9216 floats / stage
#define STG_FLT (A_STG + B_STG)         // 13824 floats
#define NSTG (KT/BK)                    // 56
#define SMEM_GEMM (3*STG_FLT*4)         // 165888 bytes

__global__ void __launch_bounds__(256, 1) k_gemm_mma(const float* __restrict__ bias)
{
    extern __shared__ float sm[];
    const uint32_t smb = smem_u32(sm);
    const int tid  = threadIdx.x;
    const int brow = blockIdx.x * BM;
    const int w    = tid >> 5;
    const int lane = tid & 31;
    const int g    = lane >> 2;        // 0..7
    const int r    = lane & 3;         // 0..3
    const int warpM = (w >> 2) * 64;   // 0 / 64
    const int warpN = (w & 3) * 64;    // 0 / 64 / 128 / 192

    // --- per-thread cp.async plan (byte offsets within a stage) ---
    const float* a_src[4]; uint32_t a_dst[4];
    #pragma unroll
    for (int i = 0; i < 4; i++){
        int c = tid + i*256;           // 0..1023  (128 rows x 8 quads)
        int row = c >> 3, q = c & 7;
        a_src[i] = g_A + (size_t)(brow + row)*KT + q*4;
        a_dst[i] = (uint32_t)(row*LDT + q*4) * 4;
    }
    const float* b_src[8]; uint32_t b_dst[8];
    #pragma unroll
    for (int i = 0; i < 8; i++){
        int c = tid + i*256;           // 0..2047  (256 rows x 8 quads)
        int row = c >> 3, q = c & 7;
        b_src[i] = g_Bt + (size_t)row*KT + q*4;
        b_dst[i] = (uint32_t)(A_STG + row*LDT + q*4) * 4;
    }

    #define LOAD_STAGE(s) do { \
        uint32_t _b = smb + (uint32_t)((s) % 3) * (STG_FLT*4); \
        int _k = (s) * BK; \
        _Pragma("unroll") \
        for (int _i = 0; _i < 4; _i++) CP_ASYNC16(_b + a_dst[_i], a_src[_i] + _k); \
        _Pragma("unroll") \
        for (int _i = 0; _i < 8; _i++) CP_ASYNC16(_b + b_dst[_i], b_src[_i] + _k); \
    } while(0)

    float acc[4][8][4];
    #pragma unroll
    for (int i = 0; i < 4; i++)
        #pragma unroll
        for (int j = 0; j < 8; j++)
            #pragma unroll
            for (int q = 0; q < 4; q++) acc[i][j][q] = 0.f;

    LOAD_STAGE(0); CP_COMMIT();
    LOAD_STAGE(1); CP_COMMIT();

    for (int t = 0; t < NSTG; t++){
        if (t + 2 < NSTG) LOAD_STAGE(t + 2);
        CP_COMMIT();                   // empty group at tail keeps counting uniform
        CP_WAIT2();                    // stage t complete
        __syncthreads();
        const uint32_t* As = (const uint32_t*)(sm + (t % 3) * STG_FLT);
        const uint32_t* Bs = As + A_STG;
        #pragma unroll
        for (int kk = 0; kk < BK; kk += 8){
            uint32_t a[4][4], b[8][2];
            #pragma unroll
            for (int i = 0; i < 4; i++){
                int m = warpM + i*16 + g;
                a[i][0] = As[m*LDT + kk + r];
                a[i][1] = As[(m+8)*LDT + kk + r];
                a[i][2] = As[m*LDT + kk + 4 + r];
                a[i][3] = As[(m+8)*LDT + kk + 4 + r];
            }
            #pragma unroll
            for (int j = 0; j < 8; j++){
                int n = warpN + j*8 + g;
                b[j][0] = Bs[n*LDT + kk + r];
                b[j][1] = Bs[n*LDT + kk + 4 + r];
            }
            #pragma unroll
            for (int i = 0; i < 4; i++)
                #pragma unroll
                for (int j = 0; j < 8; j++)
                    MMA_TF32(acc[i][j], a[i], b[j]);
        }
        __syncthreads();               // protect buffer (t%3) before reuse at t+1
    }

    // --- epilogue: bias + relu ---
    #pragma unroll
    for (int i = 0; i < 4; i++){
        int row0 = brow + warpM + i*16 + g;
        int row1 = row0 + 8;
        #pragma unroll
        for (int j = 0; j < 8; j++){
            int col = warpN + j*8 + 2*r;
            float bx = __ldg(&bias[col]);
            float by = __ldg(&bias[col+1]);
            if (row0 < NN){
                float2 v;
                v.x = fmaxf(acc[i][j][0] + bx, 0.f);
                v.y = fmaxf(acc[i][j][1] + by, 0.f);
                *(float2*)&g_h2[(size_t)row0*HH + col] = v;
            }
            if (row1 < NN){
                float2 v;
                v.x = fmaxf(acc[i][j][2] + bx, 0.f);
                v.y = fmaxf(acc[i][j][3] + by, 0.f);
                *(float2*)&g_h2[(size_t)row1*HH + col] = v;
            }
        }
    }
    #undef LOAD_STAGE
}

// ---------------- mean pool (batch_ids sorted -> segment starts) ----------
__global__ void k_gstart(const int* __restrict__ batch_ids)
{
    int i = blockIdx.x*blockDim.x + threadIdx.x;
    if (i >= NN) return;
    int b    = batch_ids[i];
    int prev = (i == 0) ? -1 : batch_ids[i-1];
    for (int g = prev + 1; g <= b; g++) g_gs[g] = i;
    if (i == NN-1)
        for (int g = b + 1; g <= NG; g++) g_gs[g] = NN;
}

__global__ void k_pool()
{
    int g = blockIdx.x, c = threadIdx.x;
    int s = g_gs[g], e = g_gs[g+1];
    float s0 = 0.f, s1 = 0.f, s2 = 0.f, s3 = 0.f;
    int i = s;
    for (; i + 3 < e; i += 4){
        s0 += g_h2[(size_t)(i  )*HH + c];
        s1 += g_h2[(size_t)(i+1)*HH + c];
        s2 += g_h2[(size_t)(i+2)*HH + c];
        s3 += g_h2[(size_t)(i+3)*HH + c];
    }
    for (; i < e; i++) s0 += g_h2[(size_t)i*HH + c];
    float sum = (s0 + s1) + (s2 + s3);
    int cnt = e - s; if (cnt < 1) cnt = 1;
    g_pool[g*HH + c] = sum / (float)cnt;
}

// ---------------- final MLP (tiny) ----------------
__global__ void k_mlp(const float* __restrict__ W, const float* __restrict__ bias,
                      float* __restrict__ outp, int mode)
{
    __shared__ float xr[HH];
    int g = blockIdx.x, c = threadIdx.x;
    xr[c] = (mode == 0) ? g_pool[g*HH + c] : g_z[g*HH + c];
    __syncthreads();
    float acc = bias[c];
    #pragma unroll 8
    for (int k = 0; k < HH; k++) acc = fmaf(xr[k], W[(size_t)k*HH + c], acc);
    if (mode == 0) g_z[g*HH + c] = fmaxf(acc, 0.f);
    else           outp[g*HH + c] = acc;
}

// ---------------- launch ----------------
extern "C" void kernel_launch(void* const* d_in, const int* in_sizes, int n_in,
                              void* d_out, int out_size)
{
    const int* x_type    = (const int*)d_in[0];
    const int* x_sub     = (const int*)d_in[1];
    const int* edges     = (const int*)d_in[2];
    const int* batch_ids = (const int*)d_in[3];
    int idx = 4;
    if (idx < n_in && in_sizes[idx] == 1) idx++;   // skip n_graphs scalar if passed
    const float* type_emb = (const float*)d_in[idx++];
    const float* sub_emb  = (const float*)d_in[idx++];
    const float* W_rel0   = (const float*)d_in[idx++];
    const float* W_self0  = (const float*)d_in[idx++];
    const float* b0       = (const float*)d_in[idx++];
    const float* W_rel1   = (const float*)d_in[idx++];
    const float* W_self1  = (const float*)d_in[idx++];
    const float* b1       = (const float*)d_in[idx++];
    const float* pW1      = (const float*)d_in[idx++];
    const float* pb1      = (const float*)d_in[idx++];
    const float* pW2      = (const float*)d_in[idx++];
    const float* pb2      = (const float*)d_in[idx++];
    float* out = (float*)d_out;

    cudaFuncSetAttribute(k_gemm_mma, cudaFuncAttributeMaxDynamicSharedMemorySize, SMEM_GEMM);

    k_init    <<<(NR*NN + 255)/256, 256>>>();
    k_tables  <<<dim3(7, 260), 256>>>(type_emb, sub_emb, W_rel0, W_self0);
    k_copyBt  <<<(KT*HH + 255)/256, 256>>>(W_rel1, W_self1);
    k_hist    <<<(NE + 255)/256, 256>>>(edges);
    k_inv     <<<(NN + 255)/256, 256>>>();
    k_scan    <<<1, 1024>>>();
    k_scatter <<<(NE + 255)/256, 256>>>(edges);
    k_layer0  <<<(NN*32 + 255)/256, 256>>>(x_type, x_sub, b0);
    k_agg1    <<<(NN*32 + 255)/256, 256>>>();
    k_gemm_mma<<<NNP/128, 256, SMEM_GEMM>>>(b1);
    k_gstart  <<<(NN + 255)/256, 256>>>(batch_ids);
    k_pool    <<<NG, 256>>>();
    k_mlp     <<<NG, 256>>>(pW1, pb1, (float*)0, 0);
    k_mlp     <<<NG, 256>>>(pW2, pb2, out, 1);
}